// round 4
// baseline (speedup 1.0000x reference)
#include <cuda_runtime.h>
#include <cuda_bf16.h>
#include <mma.h>
#include <cstdint>

using namespace nvcuda;

// ---------------- problem constants ----------------
#define BB      8
#define CDIM    128
#define HH      112
#define WWID    112
#define LTOK    (HH*WWID)        // 12544
#define MTOK    (BB*LTOK)        // 100352
#define WS      7
#define NTOK    (WS*WS)          // 49
#define NWIN    2048
#define HEADS   4
#define HD      32
#define SHIFT   3
#define MLP     512

// ---------------- scratch (device globals) ----------------
__device__ float          g_xt[(size_t)MTOK*CDIM];     // token-major shortcut
__device__ __nv_bfloat16  g_xw[(size_t)MTOK*CDIM];     // LN1, window order
__device__ __nv_bfloat16  g_qkv[(size_t)MTOK*3*CDIM];  // QKV bf16, window order
__device__ float          g_y[(size_t)MTOK*CDIM];      // residual1, token order
__device__ __nv_bfloat16  g_h[(size_t)MTOK*CDIM];      // LN2 out, token order
__device__ __nv_bfloat16  g_hh[(size_t)MTOK*MLP];      // gelu(fc1)

__device__ __nv_bfloat16  g_wqkv[CDIM*3*CDIM];         // [K][N]
__device__ __nv_bfloat16  g_wproj[CDIM*CDIM];          // [K][N]
__device__ __nv_bfloat16  g_wfc1[CDIM*MLP];            // [K][N]
__device__ __nv_bfloat16  g_wfc2[MLP*CDIM];            // [K][N]
__device__ float          g_bias[HEADS*NTOK*NTOK];

// ---------------- helpers ----------------
__device__ __forceinline__ uint32_t smem_u32(const void* p) {
    uint32_t a;
    asm("{ .reg .u64 t; cvta.to.shared.u64 t, %1; cvt.u32.u64 %0, t; }" : "=r"(a) : "l"(p));
    return a;
}
__device__ __forceinline__ void cpa16(uint32_t s, const void* g) {
    asm volatile("cp.async.cg.shared.global [%0], [%1], 16;" :: "r"(s), "l"(g) : "memory");
}
__device__ __forceinline__ void cpa_commit() {
    asm volatile("cp.async.commit_group;" ::: "memory");
}
__device__ __forceinline__ float warp_sum(float v) {
#pragma unroll
    for (int o = 16; o; o >>= 1) v += __shfl_xor_sync(0xffffffffu, v, o);
    return v;
}
__device__ __forceinline__ float warp_max(float v) {
#pragma unroll
    for (int o = 16; o; o >>= 1) v = fmaxf(v, __shfl_xor_sync(0xffffffffu, v, o));
    return v;
}
__device__ __forceinline__ int win_token(int win, int n) {
    int b   = win >> 8;
    int wr  = win & 255;
    int wi  = wr >> 4, wj = wr & 15;
    int r   = n / WS,  c = n - r * WS;
    int hs  = wi * WS + r + SHIFT; if (hs >= HH)   hs  -= HH;
    int ws_ = wj * WS + c + SHIFT; if (ws_ >= WWID) ws_ -= WWID;
    return b * LTOK + hs * WWID + ws_;
}
__device__ __forceinline__ uint32_t pack2(float a, float b) {
    __nv_bfloat162 t = __floats2bfloat162_rn(a, b);
    return *reinterpret_cast<uint32_t*>(&t);
}
__device__ __forceinline__ void store_bf16x4(__nv_bfloat16* p, float a, float b, float c, float d) {
    uint2 u; u.x = pack2(a, b); u.y = pack2(c, d);
    *reinterpret_cast<uint2*>(p) = u;
}

// ---------------- setup ----------------
#define W0 (CDIM*3*CDIM)
#define W1 (CDIM*CDIM)
#define W2 (CDIM*MLP)
#define W3 (MLP*CDIM)
#define WTOT (W0+W1+W2+W3)
#define SETUP_TOT (WTOT + HEADS*NTOK*NTOK)

__global__ void k_setup(const float* __restrict__ qkv_w, const float* __restrict__ proj_w,
                        const float* __restrict__ fc1_w, const float* __restrict__ fc2_w,
                        const float* __restrict__ tbl, const int* __restrict__ relidx) {
    int i = blockIdx.x * blockDim.x + threadIdx.x;
    if (i >= SETUP_TOT) return;
    if (i < W0)           { g_wqkv[i]          = __float2bfloat16(qkv_w[i]);          return; }
    if (i < W0+W1)        { g_wproj[i-W0]      = __float2bfloat16(proj_w[i-W0]);      return; }
    if (i < W0+W1+W2)     { g_wfc1[i-W0-W1]    = __float2bfloat16(fc1_w[i-W0-W1]);    return; }
    if (i < WTOT)         { g_wfc2[i-W0-W1-W2] = __float2bfloat16(fc2_w[i-W0-W1-W2]); return; }
    int j = i - WTOT;
    int h = j / (NTOK*NTOK);
    int e = j - h * (NTOK*NTOK);
    g_bias[h*NTOK*NTOK + e] = tbl[relidx[e]*HEADS + h];
}

// ---------------- fused transpose + LN1 + window scatter ----------------
__global__ __launch_bounds__(256) void k_ln1t(const float* __restrict__ x,
                                              const float* __restrict__ g,
                                              const float* __restrict__ be) {
    __shared__ float t[CDIM*33];
    int b  = blockIdx.y;
    int l0 = blockIdx.x * 32;
    int tid = threadIdx.x;
    int lane = tid & 31, warp = tid >> 5;

    const float* xb = x + (size_t)b * CDIM * LTOK + l0;
    {
        int l = tid & 31, cg = tid >> 5;
#pragma unroll
        for (int it = 0; it < 16; it++) {
            int c = it * 8 + cg;
            t[c * 33 + l] = xb[(size_t)c * LTOK + l];
        }
    }
    __syncthreads();

    float4 gg = reinterpret_cast<const float4*>(g)[lane];
    float4 bb = reinterpret_cast<const float4*>(be)[lane];
#pragma unroll
    for (int kk = 0; kk < 4; kk++) {
        int tt = warp * 4 + kk;
        int l  = l0 + tt;
        float4 v;
        v.x = t[(lane*4+0)*33 + tt];
        v.y = t[(lane*4+1)*33 + tt];
        v.z = t[(lane*4+2)*33 + tt];
        v.w = t[(lane*4+3)*33 + tt];
        int token = b * LTOK + l;
        reinterpret_cast<float4*>(g_xt + (size_t)token * CDIM)[lane] = v;
        float s  = v.x + v.y + v.z + v.w;
        float s2 = v.x*v.x + v.y*v.y + v.z*v.z + v.w*v.w;
        s  = warp_sum(s); s2 = warp_sum(s2);
        float mean = s * (1.f / CDIM);
        float var  = s2 * (1.f / CDIM) - mean * mean;
        float inv  = rsqrtf(var + 1e-5f);
        int hh = l / WWID, ww = l - hh * WWID;
        int h2 = hh - SHIFT; if (h2 < 0) h2 += HH;
        int w2 = ww - SHIFT; if (w2 < 0) w2 += WWID;
        int win  = (b << 8) + (h2 / WS) * 16 + (w2 / WS);
        int n    = (h2 % WS) * WS + (w2 % WS);
        int wrow = win * NTOK + n;
        store_bf16x4(g_xw + (size_t)wrow * CDIM + lane * 4,
                     (v.x - mean) * inv * gg.x + bb.x,
                     (v.y - mean) * inv * gg.y + bb.y,
                     (v.z - mean) * inv * gg.z + bb.z,
                     (v.w - mean) * inv * gg.w + bb.w);
    }
}

// ---------------- fused attention + proj + residual + LN2: one block per window ----
// smem layout (dynamic, 101376 B):
//   sQKV : 64 x 384 bf16   (49152)
//   U    : union (34816): sS 64x68 f32 | sP 64x72 bf16 (at +17408)  -> later sW 128x136 bf16 / sC 64x132 f32
//   sO   : 64 x 136 bf16   (17408)
extern __shared__ __align__(16) unsigned char adyn[];

__global__ __launch_bounds__(256) void k_attn_proj(const float* __restrict__ pbias,
                                                   const float* __restrict__ n2g,
                                                   const float* __restrict__ n2b) {
    __nv_bfloat16* sQKV = reinterpret_cast<__nv_bfloat16*>(adyn);
    unsigned char* U    = adyn + 49152;
    float*         sS   = reinterpret_cast<float*>(U);
    __nv_bfloat16* sP   = reinterpret_cast<__nv_bfloat16*>(U + 17408);
    __nv_bfloat16* sW   = reinterpret_cast<__nv_bfloat16*>(U);
    float*         sC   = reinterpret_cast<float*>(U);
    __nv_bfloat16* sO   = reinterpret_cast<__nv_bfloat16*>(adyn + 49152 + 34816);

    const int win = blockIdx.x;
    const int tid = threadIdx.x;
    const int warp = tid >> 5, lane = tid & 31;

    // load QKV rows 0..48 (48 uint4 per row), zero-pad rows 49..63; zero sP
    {
        const uint4* src = reinterpret_cast<const uint4*>(g_qkv + (size_t)win * NTOK * 384);
        uint4* dst = reinterpret_cast<uint4*>(sQKV);
#pragma unroll
        for (int it = 0; it < 12; it++) {
            int idx = it * 256 + tid;          // 3072 = 64*48
            int r = idx / 48;
            uint4 v = make_uint4(0u,0u,0u,0u);
            if (r < NTOK) v = src[idx];
            dst[idx] = v;
        }
        for (int i = tid; i < 64*72/2; i += 256) reinterpret_cast<uint32_t*>(sP)[i] = 0u;
    }
    __syncthreads();

    const float scale = 0.17677669529663687f;
#pragma unroll 1
    for (int h = 0; h < HEADS; h++) {
        // S = Q K^T (64x64x32), warp tile 16x32
        {
            int wm = (warp & 3) * 16, wn = (warp >> 2) * 32;
            wmma::fragment<wmma::accumulator,16,16,16,float> s[2];
#pragma unroll
            for (int j = 0; j < 2; j++) wmma::fill_fragment(s[j], 0.f);
#pragma unroll
            for (int kk = 0; kk < 2; kk++) {
                wmma::fragment<wmma::matrix_a,16,16,16,__nv_bfloat16,wmma::row_major> qa;
                wmma::load_matrix_sync(qa, &sQKV[wm*384 + h*32 + kk*16], 384);
#pragma unroll
                for (int j = 0; j < 2; j++) {
                    wmma::fragment<wmma::matrix_b,16,16,16,__nv_bfloat16,wmma::col_major> kb;
                    wmma::load_matrix_sync(kb, &sQKV[(wn + 16*j)*384 + 128 + h*32 + kk*16], 384);
                    wmma::mma_sync(s[j], qa, kb, s[j]);
                }
            }
#pragma unroll
            for (int j = 0; j < 2; j++)
                wmma::store_matrix_sync(&sS[wm*68 + wn + 16*j], s[j], 68, wmma::mem_row_major);
        }
        __syncthreads();

        // softmax (normalized P written as bf16)
        for (int r = warp; r < NTOK; r += 8) {
            const float* brow = &g_bias[h*NTOK*NTOK + r*NTOK];
            int c2 = lane + 32;
            float v1 = sS[r*68 + lane] * scale + brow[lane];
            float v2 = (c2 < NTOK) ? sS[r*68 + c2] * scale + brow[c2] : -1e30f;
            float mx = warp_max(fmaxf(v1, v2));
            float e1 = __expf(v1 - mx);
            float e2 = (c2 < NTOK) ? __expf(v2 - mx) : 0.f;
            float rinv = 1.f / warp_sum(e1 + e2);
            sP[r*72 + lane] = __float2bfloat16(e1 * rinv);
            if (c2 < NTOK) sP[r*72 + c2] = __float2bfloat16(e2 * rinv);
        }
        __syncthreads();

        // O_h = P V (64x32x64), warp tile 16x16, staged fp32 in sS
        {
            int wm = (warp & 3) * 16, wn = (warp >> 2) * 16;
            wmma::fragment<wmma::accumulator,16,16,16,float> o;
            wmma::fill_fragment(o, 0.f);
#pragma unroll
            for (int kk = 0; kk < 4; kk++) {
                wmma::fragment<wmma::matrix_a,16,16,16,__nv_bfloat16,wmma::row_major> pa;
                wmma::load_matrix_sync(pa, &sP[wm*72 + kk*16], 72);
                wmma::fragment<wmma::matrix_b,16,16,16,__nv_bfloat16,wmma::row_major> vb;
                wmma::load_matrix_sync(vb, &sQKV[(kk*16)*384 + 256 + h*32 + wn], 384);
                wmma::mma_sync(o, pa, vb, o);
            }
            wmma::store_matrix_sync(&sS[wm*68 + wn], o, 68, wmma::mem_row_major);
        }
        __syncthreads();

        // convert to sO columns [h*32, h*32+32)
        for (int i = tid; i < 64*32; i += 256) {
            int r = i >> 5, c = i & 31;
            sO[r*136 + h*32 + c] = __float2bfloat16(sS[r*68 + c]);
        }
        __syncthreads();
    }

    // load proj weights into union region (sS/sP dead)
    {
        const uint4* src = reinterpret_cast<const uint4*>(g_wproj);   // 2048 uint4
        uint4* dst = reinterpret_cast<uint4*>(sW);
#pragma unroll
        for (int it = 0; it < 8; it++) {
            int idx = it * 256 + tid;
            int r = idx >> 4, c = idx & 15;
            dst[r*17 + c] = src[idx];
        }
    }
    __syncthreads();

    // proj: (64x128) = sO(64x128) @ sW(128x128), warp tile 16x64
    {
        int wm = (warp & 3) * 16, wn = (warp >> 2) * 64;
        wmma::fragment<wmma::accumulator,16,16,16,float> o[4];
#pragma unroll
        for (int j = 0; j < 4; j++) wmma::fill_fragment(o[j], 0.f);
#pragma unroll
        for (int kk = 0; kk < 8; kk++) {
            wmma::fragment<wmma::matrix_a,16,16,16,__nv_bfloat16,wmma::row_major> pa;
            wmma::load_matrix_sync(pa, &sO[wm*136 + kk*16], 136);
#pragma unroll
            for (int j = 0; j < 4; j++) {
                wmma::fragment<wmma::matrix_b,16,16,16,__nv_bfloat16,wmma::row_major> wb;
                wmma::load_matrix_sync(wb, &sW[(kk*16)*136 + wn + 16*j], 136);
                wmma::mma_sync(o[j], pa, wb, o[j]);
            }
        }
        __syncthreads();   // all warps done reading sW before sC overwrite
#pragma unroll
        for (int j = 0; j < 4; j++)
            wmma::store_matrix_sync(&sC[wm*132 + wn + 16*j], o[j], 132, wmma::mem_row_major);
    }
    __syncthreads();

    // epilogue: rows 0..48 -> residual + LN2, scatter to token order
    {
        float4 pb = reinterpret_cast<const float4*>(pbias)[lane];
        float4 gg = reinterpret_cast<const float4*>(n2g)[lane];
        float4 lb = reinterpret_cast<const float4*>(n2b)[lane];
        for (int r = warp; r < NTOK; r += 8) {
            int token = win_token(win, r);
            float4 v = *reinterpret_cast<float4*>(&sC[r*132 + lane*4]);
            float4 x = reinterpret_cast<const float4*>(g_xt + (size_t)token*CDIM)[lane];
            float4 y;
            y.x = v.x + pb.x + x.x;  y.y = v.y + pb.y + x.y;
            y.z = v.z + pb.z + x.z;  y.w = v.w + pb.w + x.w;
            reinterpret_cast<float4*>(g_y + (size_t)token*CDIM)[lane] = y;
            float s  = y.x + y.y + y.z + y.w;
            float s2 = y.x*y.x + y.y*y.y + y.z*y.z + y.w*y.w;
            s = warp_sum(s); s2 = warp_sum(s2);
            float mean = s * (1.f / CDIM);
            float var  = s2 * (1.f / CDIM) - mean * mean;
            float inv  = rsqrtf(var + 1e-5f);
            store_bf16x4(g_h + (size_t)token*CDIM + lane*4,
                         (y.x - mean) * inv * gg.x + lb.x,
                         (y.y - mean) * inv * gg.y + lb.y,
                         (y.z - mean) * inv * gg.z + lb.z,
                         (y.w - mean) * inv * gg.w + lb.w);
        }
    }
}

// ---------------- cp.async double-buffered WMMA GEMM, 128x128 tiles ----------------
// EPI: 0 = QKV (bias -> bf16), 2 = FC1 (bias + gelu -> bf16),
//      3 = FC2 (bias + residual -> transposed fp32 out)
#define TILEB 34816   // 128 x 136 bf16

extern __shared__ __align__(16) unsigned char gdyn[];

template<int NT128, int KT128, int EPI>
__device__ __forceinline__ void gemm_body(
    const __nv_bfloat16* __restrict__ A,
    const __nv_bfloat16* __restrict__ Bw,      // [K][N]
    const float* __restrict__ bias,
    float* __restrict__ outf)
{
    const int N = NT128 * 128, K = KT128 * 128;
    const int ABUF = (KT128 > 1) ? 2 : 1;
    unsigned char* sAb = gdyn;
    unsigned char* sBb = gdyn + ABUF * TILEB;
    const uint32_t sA32 = smem_u32(sAb), sB32 = smem_u32(sBb);

    const int tid = threadIdx.x;
    const int warp = tid >> 5;
    const int bm = blockIdx.x * 128;
    const int wm = (warp & 3) * 32, wn = (warp >> 2) * 64;
    const int G = NT128 * KT128;

    auto issue = [&](int g) {
        int nc = g / KT128, kc = g % KT128;
        {
            const __nv_bfloat16* src = Bw + (size_t)(kc*128) * N + nc*128;
            uint32_t sb = sB32 + (uint32_t)(g & 1) * TILEB;
#pragma unroll
            for (int it = 0; it < 8; it++) {
                int idx = it * 256 + tid;
                int r = idx >> 4, c = idx & 15;
                cpa16(sb + r*272 + c*16, src + (size_t)r * N + c*8);
            }
        }
        if (KT128 > 1 || g == 0) {
            const __nv_bfloat16* src = A + (size_t)bm * K + kc*128;
            uint32_t sa = sA32 + (KT128 > 1 ? (uint32_t)(g & 1) * TILEB : 0u);
#pragma unroll
            for (int it = 0; it < 8; it++) {
                int idx = it * 256 + tid;
                int r = idx >> 4, c = idx & 15;
                cpa16(sa + r*272 + c*16, src + (size_t)r * K + c*8);
            }
        }
        cpa_commit();
    };

    issue(0);
    if (G > 1) issue(1);

    wmma::fragment<wmma::accumulator,16,16,16,float> acc[2][4];

#pragma unroll 1
    for (int g = 0; g < G; g++) {
        int kc = g % KT128;
        if (g + 1 < G) asm volatile("cp.async.wait_group 1;" ::: "memory");
        else           asm volatile("cp.async.wait_group 0;" ::: "memory");
        __syncthreads();

        if (kc == 0) {
#pragma unroll
            for (int i = 0; i < 2; i++)
#pragma unroll
                for (int j = 0; j < 4; j++) wmma::fill_fragment(acc[i][j], 0.f);
        }
        const __nv_bfloat16* pA = reinterpret_cast<const __nv_bfloat16*>(
            sAb + (KT128 > 1 ? (size_t)(g & 1) * TILEB : 0));
        const __nv_bfloat16* pB = reinterpret_cast<const __nv_bfloat16*>(
            sBb + (size_t)(g & 1) * TILEB);
#pragma unroll
        for (int kk = 0; kk < 8; kk++) {
            wmma::fragment<wmma::matrix_a,16,16,16,__nv_bfloat16,wmma::row_major> af[2];
#pragma unroll
            for (int i = 0; i < 2; i++)
                wmma::load_matrix_sync(af[i], &pA[(wm + 16*i)*136 + kk*16], 136);
#pragma unroll
            for (int j = 0; j < 4; j++) {
                wmma::fragment<wmma::matrix_b,16,16,16,__nv_bfloat16,wmma::row_major> bf;
                wmma::load_matrix_sync(bf, &pB[(kk*16)*136 + wn + 16*j], 136);
#pragma unroll
                for (int i = 0; i < 2; i++)
                    wmma::mma_sync(acc[i][j], af[i], bf, acc[i][j]);
            }
        }
        __syncthreads();

        if (kc == KT128 - 1) {
            int nc = g / KT128;
            float* sC = reinterpret_cast<float*>(sBb + (size_t)(g & 1) * TILEB);
#pragma unroll
            for (int h2 = 0; h2 < 2; h2++) {
                if (((warp & 3) >> 1) == h2) {
                    int wl = wm - 64 * h2;
#pragma unroll
                    for (int i = 0; i < 2; i++)
#pragma unroll
                        for (int j = 0; j < 4; j++)
                            wmma::store_matrix_sync(&sC[(wl + 16*i)*132 + wn + 16*j],
                                                    acc[i][j], 132, wmma::mem_row_major);
                }
                __syncthreads();

                if (EPI == 0 || EPI == 2) {
                    const int ncol = (EPI == 0) ? 3*CDIM : MLP;
                    __nv_bfloat16* base = (EPI == 0) ? g_qkv : g_hh;
                    for (int e = tid; e < 64*128; e += 256) {
                        int r = e >> 7, c = e & 127;
                        float v = sC[r*132 + c] + bias[nc*128 + c];
                        if (EPI == 2) v = 0.5f * v * (1.f + erff(v * 0.70710678118654752f));
                        base[(size_t)(bm + 64*h2 + r)*ncol + nc*128 + c] = __float2bfloat16(v);
                    }
                } else {
                    int row0 = bm + 64*h2;
                    for (int e = tid; e < 64*128; e += 256) {
                        int r = e >> 7, c = e & 127;
                        sC[r*132 + c] += bias[c] + g_y[(size_t)(row0 + r)*CDIM + c];
                    }
                    __syncthreads();
                    int b  = row0 / LTOK;
                    int l0 = row0 - b * LTOK;
                    float* ob = outf + (size_t)b * CDIM * LTOK + l0;
                    int l = tid & 63, cb = tid >> 6;
#pragma unroll
                    for (int it = 0; it < 32; it++) {
                        int c = it * 4 + cb;
                        ob[(size_t)c * LTOK + l] = sC[l*132 + c];
                    }
                }
                __syncthreads();
            }
        }
        if (g + 2 < G) issue(g + 2);
    }
}

__global__ __launch_bounds__(256) void k_gemm_qkv(const float* bias) {
    gemm_body<3,1,0>(g_xw, g_wqkv, bias, nullptr);
}
__global__ __launch_bounds__(256) void k_gemm_fc1(const float* bias) {
    gemm_body<4,1,2>(g_h, g_wfc1, bias, nullptr);
}
__global__ __launch_bounds__(256) void k_gemm_fc2(const float* bias, float* out) {
    gemm_body<1,4,3>(g_hh, g_wfc2, bias, out);
}

// ---------------- launch ----------------
extern "C" void kernel_launch(void* const* d_in, const int* in_sizes, int n_in,
                              void* d_out, int out_size) {
    const float* x      = (const float*)d_in[0];
    const float* n1g    = (const float*)d_in[1];
    const float* n1b    = (const float*)d_in[2];
    const float* qkv_w  = (const float*)d_in[3];
    const float* qkv_b  = (const float*)d_in[4];
    const float* tbl    = (const float*)d_in[5];
    const int*   relidx = (const int*)d_in[6];
    const float* proj_w = (const float*)d_in[7];
    const float* proj_b = (const float*)d_in[8];
    const float* n2g    = (const float*)d_in[9];
    const float* n2b    = (const float*)d_in[10];
    const float* fc1_w  = (const float*)d_in[11];
    const float* fc1_b  = (const float*)d_in[12];
    const float* fc2_w  = (const float*)d_in[13];
    const float* fc2_b  = (const float*)d_in[14];
    float* out = (float*)d_out;

    const int GSM_G1  = 3 * TILEB;        // 104448: qkv/fc1 (A + 2B)
    const int GSM_FC2 = 4 * TILEB;        // 139264: fc2 (2A + 2B)
    const int GSM_ATT = 49152 + 34816 + 17408;   // 101376

    cudaFuncSetAttribute(k_gemm_qkv,  cudaFuncAttributeMaxDynamicSharedMemorySize, GSM_G1);
    cudaFuncSetAttribute(k_gemm_fc1,  cudaFuncAttributeMaxDynamicSharedMemorySize, GSM_G1);
    cudaFuncSetAttribute(k_gemm_fc2,  cudaFuncAttributeMaxDynamicSharedMemorySize, GSM_FC2);
    cudaFuncSetAttribute(k_attn_proj, cudaFuncAttributeMaxDynamicSharedMemorySize, GSM_ATT);

    k_setup<<<(SETUP_TOT + 255)/256, 256>>>(qkv_w, proj_w, fc1_w, fc2_w, tbl, relidx);
    k_ln1t<<<dim3(LTOK/32, BB), 256>>>(x, n1g, n1b);
    k_gemm_qkv<<<MTOK/128, 256, GSM_G1>>>(qkv_b);
    k_attn_proj<<<NWIN, 256, GSM_ATT>>>(proj_b, n2g, n2b);
    k_gemm_fc1<<<MTOK/128, 256, GSM_G1>>>(fc1_b);
    k_gemm_fc2<<<MTOK/128, 256, GSM_FC2>>>(fc2_b, out);
}

// round 5
// speedup vs baseline: 1.0520x; 1.0520x over previous
#include <cuda_runtime.h>
#include <cuda_bf16.h>
#include <mma.h>
#include <cstdint>

using namespace nvcuda;

// ---------------- problem constants ----------------
#define BB      8
#define CDIM    128
#define HH      112
#define WWID    112
#define LTOK    (HH*WWID)        // 12544
#define MTOK    (BB*LTOK)        // 100352
#define WS      7
#define NTOK    (WS*WS)          // 49
#define NWIN    2048
#define HEADS   4
#define HD      32
#define SHIFT   3
#define MLP     512

// ---------------- scratch (device globals) ----------------
__device__ float          g_xt[(size_t)MTOK*CDIM];     // token-major shortcut
__device__ __nv_bfloat16  g_xw[(size_t)MTOK*CDIM];     // LN1, window order
__device__ __nv_bfloat16  g_qkv[(size_t)MTOK*3*CDIM];  // QKV bf16, window order
__device__ __nv_bfloat16  g_attnout[(size_t)MTOK*CDIM];// attention out, window order
__device__ float          g_y[(size_t)MTOK*CDIM];      // residual1, token order
__device__ __nv_bfloat16  g_h[(size_t)MTOK*CDIM];      // LN2 out, token order
__device__ __nv_bfloat16  g_hh[(size_t)MTOK*MLP];      // gelu(fc1)

__device__ __nv_bfloat16  g_wqkv[CDIM*3*CDIM];         // [K][N]
__device__ __nv_bfloat16  g_wproj[CDIM*CDIM];          // [K][N]
__device__ __nv_bfloat16  g_wfc1[CDIM*MLP];            // [K][N]
__device__ __nv_bfloat16  g_wfc2[MLP*CDIM];            // [K][N]
__device__ float          g_bias[HEADS*NTOK*NTOK];

// ---------------- helpers ----------------
__device__ __forceinline__ uint32_t smem_u32(const void* p) {
    uint32_t a;
    asm("{ .reg .u64 t; cvta.to.shared.u64 t, %1; cvt.u32.u64 %0, t; }" : "=r"(a) : "l"(p));
    return a;
}
__device__ __forceinline__ void cpa16(uint32_t s, const void* g) {
    asm volatile("cp.async.cg.shared.global [%0], [%1], 16;" :: "r"(s), "l"(g) : "memory");
}
__device__ __forceinline__ void cpa_commit() {
    asm volatile("cp.async.commit_group;" ::: "memory");
}
__device__ __forceinline__ float warp_sum(float v) {
#pragma unroll
    for (int o = 16; o; o >>= 1) v += __shfl_xor_sync(0xffffffffu, v, o);
    return v;
}
__device__ __forceinline__ float warp_max(float v) {
#pragma unroll
    for (int o = 16; o; o >>= 1) v = fmaxf(v, __shfl_xor_sync(0xffffffffu, v, o));
    return v;
}
__device__ __forceinline__ int winrow_to_token(int i) {
    int win = i / NTOK, n = i - win * NTOK;
    int b   = win >> 8;
    int wr  = win & 255;
    int wi  = wr >> 4, wj = wr & 15;
    int r   = n / WS,  c = n - r * WS;
    int hs  = wi * WS + r + SHIFT; if (hs >= HH)   hs  -= HH;
    int ws_ = wj * WS + c + SHIFT; if (ws_ >= WWID) ws_ -= WWID;
    return b * LTOK + hs * WWID + ws_;
}
__device__ __forceinline__ uint32_t pack2(float a, float b) {
    __nv_bfloat162 t = __floats2bfloat162_rn(a, b);
    return *reinterpret_cast<uint32_t*>(&t);
}
__device__ __forceinline__ void store_bf16x4(__nv_bfloat16* p, float a, float b, float c, float d) {
    uint2 u; u.x = pack2(a, b); u.y = pack2(c, d);
    *reinterpret_cast<uint2*>(p) = u;
}

// ---------------- setup ----------------
#define W0 (CDIM*3*CDIM)
#define W1 (CDIM*CDIM)
#define W2 (CDIM*MLP)
#define W3 (MLP*CDIM)
#define WTOT (W0+W1+W2+W3)
#define SETUP_TOT (WTOT + HEADS*NTOK*NTOK)

__global__ void k_setup(const float* __restrict__ qkv_w, const float* __restrict__ proj_w,
                        const float* __restrict__ fc1_w, const float* __restrict__ fc2_w,
                        const float* __restrict__ tbl, const int* __restrict__ relidx) {
    int i = blockIdx.x * blockDim.x + threadIdx.x;
    if (i >= SETUP_TOT) return;
    if (i < W0)           { g_wqkv[i]          = __float2bfloat16(qkv_w[i]);          return; }
    if (i < W0+W1)        { g_wproj[i-W0]      = __float2bfloat16(proj_w[i-W0]);      return; }
    if (i < W0+W1+W2)     { g_wfc1[i-W0-W1]    = __float2bfloat16(fc1_w[i-W0-W1]);    return; }
    if (i < WTOT)         { g_wfc2[i-W0-W1-W2] = __float2bfloat16(fc2_w[i-W0-W1-W2]); return; }
    int j = i - WTOT;
    int h = j / (NTOK*NTOK);
    int e = j - h * (NTOK*NTOK);
    g_bias[h*NTOK*NTOK + e] = tbl[relidx[e]*HEADS + h];
}

// ---------------- fused transpose + LN1 + window scatter ----------------
__global__ __launch_bounds__(256) void k_ln1t(const float* __restrict__ x,
                                              const float* __restrict__ g,
                                              const float* __restrict__ be) {
    __shared__ float t[CDIM*33];
    int b  = blockIdx.y;
    int l0 = blockIdx.x * 32;
    int tid = threadIdx.x;
    int lane = tid & 31, warp = tid >> 5;

    const float* xb = x + (size_t)b * CDIM * LTOK + l0;
    {
        int l = tid & 31, cg = tid >> 5;
#pragma unroll
        for (int it = 0; it < 16; it++) {
            int c = it * 8 + cg;
            t[c * 33 + l] = xb[(size_t)c * LTOK + l];
        }
    }
    __syncthreads();

    float4 gg = reinterpret_cast<const float4*>(g)[lane];
    float4 bb = reinterpret_cast<const float4*>(be)[lane];
#pragma unroll
    for (int kk = 0; kk < 4; kk++) {
        int tt = warp * 4 + kk;
        int l  = l0 + tt;
        float4 v;
        v.x = t[(lane*4+0)*33 + tt];
        v.y = t[(lane*4+1)*33 + tt];
        v.z = t[(lane*4+2)*33 + tt];
        v.w = t[(lane*4+3)*33 + tt];
        int token = b * LTOK + l;
        reinterpret_cast<float4*>(g_xt + (size_t)token * CDIM)[lane] = v;
        float s  = v.x + v.y + v.z + v.w;
        float s2 = v.x*v.x + v.y*v.y + v.z*v.z + v.w*v.w;
        s  = warp_sum(s); s2 = warp_sum(s2);
        float mean = s * (1.f / CDIM);
        float var  = s2 * (1.f / CDIM) - mean * mean;
        float inv  = rsqrtf(var + 1e-5f);
        int hh = l / WWID, ww = l - hh * WWID;
        int h2 = hh - SHIFT; if (h2 < 0) h2 += HH;
        int w2 = ww - SHIFT; if (w2 < 0) w2 += WWID;
        int win  = (b << 8) + (h2 / WS) * 16 + (w2 / WS);
        int n    = (h2 % WS) * WS + (w2 % WS);
        int wrow = win * NTOK + n;
        store_bf16x4(g_xw + (size_t)wrow * CDIM + lane * 4,
                     (v.x - mean) * inv * gg.x + bb.x,
                     (v.y - mean) * inv * gg.y + bb.y,
                     (v.z - mean) * inv * gg.z + bb.z,
                     (v.w - mean) * inv * gg.w + bb.w);
    }
}

// ---------------- WMMA attention: one block per (window, head) ----------------
__global__ __launch_bounds__(128) void k_attn() {
    __shared__ __nv_bfloat16 sQ[64*40];
    __shared__ __nv_bfloat16 sK[64*40];
    __shared__ __nv_bfloat16 sV[64*40];
    __shared__ float         sS[64*68];
    __shared__ __nv_bfloat16 sP[64*72];
    __shared__ float         srinv[64];

    int bid  = blockIdx.x;
    int win  = bid >> 2;
    int head = bid & 3;
    int tid  = threadIdx.x;
    int warp = tid >> 5, lane = tid & 31;

    const __nv_bfloat16 zz = __float2bfloat16(0.f);
#pragma unroll
    for (int it = 0; it < 16; it++) {
        int e = it * 128 + tid;
        int n = e >> 5, d = e & 31;
        __nv_bfloat16 q = zz, k = zz, v = zz;
        if (n < NTOK) {
            size_t base = ((size_t)win * NTOK + n) * (3*CDIM) + head * HD + d;
            q = g_qkv[base];
            k = g_qkv[base + CDIM];
            v = g_qkv[base + 2*CDIM];
        }
        sQ[n*40 + d] = q;
        sK[n*40 + d] = k;
        sV[n*40 + d] = v;
    }
    // zero P rows 49..63 (A-rows feeding ignored output rows stay finite)
    for (int e = tid; e < (64-NTOK)*72/2; e += 128)
        reinterpret_cast<uint32_t*>(sP + NTOK*72)[e] = 0u;
    __syncthreads();

    // S = Q K^T
    {
        int wrow = warp * 16;
        wmma::fragment<wmma::accumulator,16,16,16,float> s[4];
#pragma unroll
        for (int j = 0; j < 4; j++) wmma::fill_fragment(s[j], 0.f);
#pragma unroll
        for (int i = 0; i < 2; i++) {
            wmma::fragment<wmma::matrix_a,16,16,16,__nv_bfloat16,wmma::row_major> qa;
            wmma::load_matrix_sync(qa, &sQ[wrow*40 + 16*i], 40);
#pragma unroll
            for (int j = 0; j < 4; j++) {
                wmma::fragment<wmma::matrix_b,16,16,16,__nv_bfloat16,wmma::col_major> kb;
                wmma::load_matrix_sync(kb, &sK[(16*j)*40 + 16*i], 40);
                wmma::mma_sync(s[j], qa, kb, s[j]);
            }
        }
#pragma unroll
        for (int j = 0; j < 4; j++)
            wmma::store_matrix_sync(&sS[wrow*68 + 16*j], s[j], 68, wmma::mem_row_major);
    }
    __syncthreads();

    // warp-parallel softmax (unnormalized P, deferred 1/sum); pads cols 49..63 with 0
    {
        const float scale = 0.17677669529663687f;
        for (int r = warp; r < NTOK; r += 4) {
            const float* brow = &g_bias[head*NTOK*NTOK + r*NTOK];
            int c2 = lane + 32;
            float v1 = sS[r*68 + lane] * scale + brow[lane];
            float v2 = (c2 < NTOK) ? sS[r*68 + c2] * scale + brow[c2] : -1e30f;
            float mx = warp_max(fmaxf(v1, v2));
            float e1 = __expf(v1 - mx);
            float e2 = (c2 < NTOK) ? __expf(v2 - mx) : 0.f;
            float sum = warp_sum(e1 + e2);
            sP[r*72 + lane] = __float2bfloat16(e1);
            sP[r*72 + c2]   = __float2bfloat16(e2);
            if (lane == 0) srinv[r] = 1.f / sum;
        }
    }
    __syncthreads();

    // O = P V
    {
        int wrow = warp * 16;
        wmma::fragment<wmma::accumulator,16,16,16,float> o[2];
#pragma unroll
        for (int j = 0; j < 2; j++) wmma::fill_fragment(o[j], 0.f);
#pragma unroll
        for (int i = 0; i < 4; i++) {
            wmma::fragment<wmma::matrix_a,16,16,16,__nv_bfloat16,wmma::row_major> pa;
            wmma::load_matrix_sync(pa, &sP[wrow*72 + 16*i], 72);
#pragma unroll
            for (int j = 0; j < 2; j++) {
                wmma::fragment<wmma::matrix_b,16,16,16,__nv_bfloat16,wmma::row_major> vb;
                wmma::load_matrix_sync(vb, &sV[(16*i)*40 + 16*j], 40);
                wmma::mma_sync(o[j], pa, vb, o[j]);
            }
        }
        __syncthreads();
#pragma unroll
        for (int j = 0; j < 2; j++)
            wmma::store_matrix_sync(&sS[wrow*68 + 16*j], o[j], 68, wmma::mem_row_major);
    }
    __syncthreads();

#pragma unroll
    for (int it = 0; it < 13; it++) {
        int e = it * 128 + tid;
        if (e < NTOK * HD) {
            int n = e >> 5, d = e & 31;
            g_attnout[((size_t)win * NTOK + n) * CDIM + head * HD + d] =
                __float2bfloat16(sS[n*68 + d] * srinv[n]);
        }
    }
}

// ---------------- cp.async double-buffered WMMA GEMM, 128x128 tiles ----------------
// EPI: 0 = QKV (bias -> bf16), 1 = PROJ (bias + residual + LN2 scatter),
//      2 = FC1 (bias + gelu -> bf16), 3 = FC2 (bias + residual -> transposed fp32 out)
#define TILEB 34816   // 128 x 136 bf16

extern __shared__ __align__(16) unsigned char gdyn[];

template<int NT128, int KT128, int EPI>
__device__ __forceinline__ void gemm_body(
    const __nv_bfloat16* __restrict__ A,
    const __nv_bfloat16* __restrict__ Bw,      // [K][N]
    const float* __restrict__ bias,
    float* __restrict__ outf,
    const float* __restrict__ ln_g,
    const float* __restrict__ ln_b)
{
    const int N = NT128 * 128, K = KT128 * 128;
    const int ABUF = (KT128 > 1) ? 2 : 1;
    unsigned char* sAb = gdyn;
    unsigned char* sBb = gdyn + ABUF * TILEB;
    const uint32_t sA32 = smem_u32(sAb), sB32 = smem_u32(sBb);

    const int tid = threadIdx.x;
    const int warp = tid >> 5, lane = tid & 31;
    const int bm = blockIdx.x * 128;
    const int wm = (warp & 3) * 32, wn = (warp >> 2) * 64;
    const int G = NT128 * KT128;

    auto issue = [&](int g) {
        int nc = g / KT128, kc = g % KT128;
        {
            const __nv_bfloat16* src = Bw + (size_t)(kc*128) * N + nc*128;
            uint32_t sb = sB32 + (uint32_t)(g & 1) * TILEB;
#pragma unroll
            for (int it = 0; it < 8; it++) {
                int idx = it * 256 + tid;
                int r = idx >> 4, c = idx & 15;
                cpa16(sb + r*272 + c*16, src + (size_t)r * N + c*8);
            }
        }
        if (KT128 > 1 || g == 0) {
            const __nv_bfloat16* src = A + (size_t)bm * K + kc*128;
            uint32_t sa = sA32 + (KT128 > 1 ? (uint32_t)(g & 1) * TILEB : 0u);
#pragma unroll
            for (int it = 0; it < 8; it++) {
                int idx = it * 256 + tid;
                int r = idx >> 4, c = idx & 15;
                cpa16(sa + r*272 + c*16, src + (size_t)r * K + c*8);
            }
        }
        cpa_commit();
    };

    issue(0);
    if (G > 1) issue(1);

    wmma::fragment<wmma::accumulator,16,16,16,float> acc[2][4];

#pragma unroll 1
    for (int g = 0; g < G; g++) {
        int kc = g % KT128;
        if (g + 1 < G) asm volatile("cp.async.wait_group 1;" ::: "memory");
        else           asm volatile("cp.async.wait_group 0;" ::: "memory");
        __syncthreads();

        if (kc == 0) {
#pragma unroll
            for (int i = 0; i < 2; i++)
#pragma unroll
                for (int j = 0; j < 4; j++) wmma::fill_fragment(acc[i][j], 0.f);
        }
        const __nv_bfloat16* pA = reinterpret_cast<const __nv_bfloat16*>(
            sAb + (KT128 > 1 ? (size_t)(g & 1) * TILEB : 0));
        const __nv_bfloat16* pB = reinterpret_cast<const __nv_bfloat16*>(
            sBb + (size_t)(g & 1) * TILEB);
#pragma unroll
        for (int kk = 0; kk < 8; kk++) {
            wmma::fragment<wmma::matrix_a,16,16,16,__nv_bfloat16,wmma::row_major> af[2];
#pragma unroll
            for (int i = 0; i < 2; i++)
                wmma::load_matrix_sync(af[i], &pA[(wm + 16*i)*136 + kk*16], 136);
#pragma unroll
            for (int j = 0; j < 4; j++) {
                wmma::fragment<wmma::matrix_b,16,16,16,__nv_bfloat16,wmma::row_major> bf;
                wmma::load_matrix_sync(bf, &pB[(kk*16)*136 + wn + 16*j], 136);
#pragma unroll
                for (int i = 0; i < 2; i++)
                    wmma::mma_sync(acc[i][j], af[i], bf, acc[i][j]);
            }
        }
        __syncthreads();

        if (kc == KT128 - 1) {
            int nc = g / KT128;
            float* sC = reinterpret_cast<float*>(sBb + (size_t)(g & 1) * TILEB);
#pragma unroll
            for (int h2 = 0; h2 < 2; h2++) {
                if (((warp & 3) >> 1) == h2) {
                    int wl = wm - 64 * h2;
#pragma unroll
                    for (int i = 0; i < 2; i++)
#pragma unroll
                        for (int j = 0; j < 4; j++)
                            wmma::store_matrix_sync(&sC[(wl + 16*i)*132 + wn + 16*j],
                                                    acc[i][j], 132, wmma::mem_row_major);
                }
                __syncthreads();

                if (EPI == 0 || EPI == 2) {
                    const int ncol = (EPI == 0) ? 3*CDIM : MLP;
                    __nv_bfloat16* base = (EPI == 0) ? g_qkv : g_hh;
                    for (int e = tid; e < 64*128; e += 256) {
                        int r = e >> 7, c = e & 127;
                        float v = sC[r*132 + c] + bias[nc*128 + c];
                        if (EPI == 2) v = 0.5f * v * (1.f + erff(v * 0.70710678118654752f));
                        base[(size_t)(bm + 64*h2 + r)*ncol + nc*128 + c] = __float2bfloat16(v);
                    }
                } else if (EPI == 1) {
                    // bias + residual + LN2, window->token scatter; warp per row
                    float4 pb = reinterpret_cast<const float4*>(bias)[lane];
                    float4 gg = reinterpret_cast<const float4*>(ln_g)[lane];
                    float4 lb = reinterpret_cast<const float4*>(ln_b)[lane];
                    for (int r = warp; r < 64; r += 8) {
                        int token = winrow_to_token(bm + 64*h2 + r);
                        float4 v = *reinterpret_cast<float4*>(&sC[r*132 + lane*4]);
                        float4 x = reinterpret_cast<const float4*>(g_xt + (size_t)token*CDIM)[lane];
                        float4 y;
                        y.x = v.x + pb.x + x.x;  y.y = v.y + pb.y + x.y;
                        y.z = v.z + pb.z + x.z;  y.w = v.w + pb.w + x.w;
                        reinterpret_cast<float4*>(g_y + (size_t)token*CDIM)[lane] = y;
                        float s  = y.x + y.y + y.z + y.w;
                        float s2 = y.x*y.x + y.y*y.y + y.z*y.z + y.w*y.w;
                        s = warp_sum(s); s2 = warp_sum(s2);
                        float mean = s * (1.f / CDIM);
                        float var  = s2 * (1.f / CDIM) - mean * mean;
                        float inv  = rsqrtf(var + 1e-5f);
                        store_bf16x4(g_h + (size_t)token*CDIM + lane*4,
                                     (y.x - mean) * inv * gg.x + lb.x,
                                     (y.y - mean) * inv * gg.y + lb.y,
                                     (y.z - mean) * inv * gg.z + lb.z,
                                     (y.w - mean) * inv * gg.w + lb.w);
                    }
                } else {
                    int row0 = bm + 64*h2;
                    for (int e = tid; e < 64*128; e += 256) {
                        int r = e >> 7, c = e & 127;
                        sC[r*132 + c] += bias[c] + g_y[(size_t)(row0 + r)*CDIM + c];
                    }
                    __syncthreads();
                    int b  = row0 / LTOK;
                    int l0 = row0 - b * LTOK;
                    float* ob = outf + (size_t)b * CDIM * LTOK + l0;
                    int l = tid & 63, cb = tid >> 6;
#pragma unroll
                    for (int it = 0; it < 32; it++) {
                        int c = it * 4 + cb;
                        ob[(size_t)c * LTOK + l] = sC[l*132 + c];
                    }
                }
                __syncthreads();
            }
        }
        if (g + 2 < G) issue(g + 2);
    }
}

__global__ __launch_bounds__(256) void k_gemm_qkv(const float* bias) {
    gemm_body<3,1,0>(g_xw, g_wqkv, bias, nullptr, nullptr, nullptr);
}
__global__ __launch_bounds__(256) void k_gemm_proj(const float* bias, const float* g, const float* b2) {
    gemm_body<1,1,1>(g_attnout, g_wproj, bias, nullptr, g, b2);
}
__global__ __launch_bounds__(256) void k_gemm_fc1(const float* bias) {
    gemm_body<4,1,2>(g_h, g_wfc1, bias, nullptr, nullptr, nullptr);
}
__global__ __launch_bounds__(256) void k_gemm_fc2(const float* bias, float* out) {
    gemm_body<1,4,3>(g_hh, g_wfc2, bias, out, nullptr, nullptr);
}

// ---------------- launch ----------------
extern "C" void kernel_launch(void* const* d_in, const int* in_sizes, int n_in,
                              void* d_out, int out_size) {
    const float* x      = (const float*)d_in[0];
    const float* n1g    = (const float*)d_in[1];
    const float* n1b    = (const float*)d_in[2];
    const float* qkv_w  = (const float*)d_in[3];
    const float* qkv_b  = (const float*)d_in[4];
    const float* tbl    = (const float*)d_in[5];
    const int*   relidx = (const int*)d_in[6];
    const float* proj_w = (const float*)d_in[7];
    const float* proj_b = (const float*)d_in[8];
    const float* n2g    = (const float*)d_in[9];
    const float* n2b    = (const float*)d_in[10];
    const float* fc1_w  = (const float*)d_in[11];
    const float* fc1_b  = (const float*)d_in[12];
    const float* fc2_w  = (const float*)d_in[13];
    const float* fc2_b  = (const float*)d_in[14];
    float* out = (float*)d_out;

    const int GSM_G1  = 3 * TILEB;        // 104448: qkv/proj/fc1 (A + 2B)
    const int GSM_FC2 = 4 * TILEB;        // 139264: fc2 (2A + 2B)

    cudaFuncSetAttribute(k_gemm_qkv,  cudaFuncAttributeMaxDynamicSharedMemorySize, GSM_G1);
    cudaFuncSetAttribute(k_gemm_proj, cudaFuncAttributeMaxDynamicSharedMemorySize, GSM_G1);
    cudaFuncSetAttribute(k_gemm_fc1,  cudaFuncAttributeMaxDynamicSharedMemorySize, GSM_G1);
    cudaFuncSetAttribute(k_gemm_fc2,  cudaFuncAttributeMaxDynamicSharedMemorySize, GSM_FC2);

    k_setup<<<(SETUP_TOT + 255)/256, 256>>>(qkv_w, proj_w, fc1_w, fc2_w, tbl, relidx);
    k_ln1t<<<dim3(LTOK/32, BB), 256>>>(x, n1g, n1b);
    k_gemm_qkv<<<MTOK/128, 256, GSM_G1>>>(qkv_b);
    k_attn<<<NWIN*HEADS, 128>>>();
    k_gemm_proj<<<MTOK/128, 256, GSM_G1>>>(proj_b, n2g, n2b);
    k_gemm_fc1<<<MTOK/128, 256, GSM_G1>>>(fc1_b);
    k_gemm_fc2<<<MTOK/128, 256, GSM_FC2>>>(fc2_b, out);
}

// round 6
// speedup vs baseline: 1.0834x; 1.0298x over previous
#include <cuda_runtime.h>
#include <cuda_bf16.h>
#include <mma.h>
#include <cstdint>

using namespace nvcuda;

// ---------------- problem constants ----------------
#define BB      8
#define CDIM    128
#define HH      112
#define WWID    112
#define LTOK    (HH*WWID)        // 12544
#define MTOK    (BB*LTOK)        // 100352
#define WS      7
#define NTOK    (WS*WS)          // 49
#define NWIN    2048
#define HEADS   4
#define HD      32
#define SHIFT   3
#define MLP     512

// ---------------- scratch (device globals) ----------------
__device__ float          g_xt[(size_t)MTOK*CDIM];     // token-major shortcut
__device__ __nv_bfloat16  g_xw[(size_t)MTOK*CDIM];     // LN1, window order
__device__ __nv_bfloat16  g_qkv[(size_t)MTOK*3*CDIM];  // QKV bf16, window order
__device__ __nv_bfloat16  g_attnout[(size_t)MTOK*CDIM];// attention out, window order
__device__ float          g_y[(size_t)MTOK*CDIM];      // residual1, token order
__device__ __nv_bfloat16  g_h[(size_t)MTOK*CDIM];      // LN2 out, token order
__device__ __nv_bfloat16  g_hh[(size_t)MTOK*MLP];      // gelu(fc1)

__device__ __nv_bfloat16  g_wqkv[CDIM*3*CDIM];         // [K][N]
__device__ __nv_bfloat16  g_wproj[CDIM*CDIM];          // [K][N]
__device__ __nv_bfloat16  g_wfc1[CDIM*MLP];            // [K][N]
__device__ __nv_bfloat16  g_wfc2[MLP*CDIM];            // [K][N]
__device__ float          g_bias[HEADS*NTOK*NTOK];

// ---------------- helpers ----------------
__device__ __forceinline__ uint32_t smem_u32(const void* p) {
    uint32_t a;
    asm("{ .reg .u64 t; cvta.to.shared.u64 t, %1; cvt.u32.u64 %0, t; }" : "=r"(a) : "l"(p));
    return a;
}
__device__ __forceinline__ void cpa16(uint32_t s, const void* g) {
    asm volatile("cp.async.cg.shared.global [%0], [%1], 16;" :: "r"(s), "l"(g) : "memory");
}
__device__ __forceinline__ void cpa_commit() {
    asm volatile("cp.async.commit_group;" ::: "memory");
}
__device__ __forceinline__ float warp_sum(float v) {
#pragma unroll
    for (int o = 16; o; o >>= 1) v += __shfl_xor_sync(0xffffffffu, v, o);
    return v;
}
__device__ __forceinline__ float warp_max(float v) {
#pragma unroll
    for (int o = 16; o; o >>= 1) v = fmaxf(v, __shfl_xor_sync(0xffffffffu, v, o));
    return v;
}
__device__ __forceinline__ int winrow_to_token(int i) {
    int win = i / NTOK, n = i - win * NTOK;
    int b   = win >> 8;
    int wr  = win & 255;
    int wi  = wr >> 4, wj = wr & 15;
    int r   = n / WS,  c = n - r * WS;
    int hs  = wi * WS + r + SHIFT; if (hs >= HH)   hs  -= HH;
    int ws_ = wj * WS + c + SHIFT; if (ws_ >= WWID) ws_ -= WWID;
    return b * LTOK + hs * WWID + ws_;
}
__device__ __forceinline__ uint32_t pack2(float a, float b) {
    __nv_bfloat162 t = __floats2bfloat162_rn(a, b);
    return *reinterpret_cast<uint32_t*>(&t);
}
__device__ __forceinline__ void store_bf16x4(__nv_bfloat16* p, float a, float b, float c, float d) {
    uint2 u; u.x = pack2(a, b); u.y = pack2(c, d);
    *reinterpret_cast<uint2*>(p) = u;
}

// ---------------- setup ----------------
#define W0 (CDIM*3*CDIM)
#define W1 (CDIM*CDIM)
#define W2 (CDIM*MLP)
#define W3 (MLP*CDIM)
#define WTOT (W0+W1+W2+W3)
#define SETUP_TOT (WTOT + HEADS*NTOK*NTOK)

__global__ void k_setup(const float* __restrict__ qkv_w, const float* __restrict__ proj_w,
                        const float* __restrict__ fc1_w, const float* __restrict__ fc2_w,
                        const float* __restrict__ tbl, const int* __restrict__ relidx) {
    int i = blockIdx.x * blockDim.x + threadIdx.x;
    if (i >= SETUP_TOT) return;
    if (i < W0)           { g_wqkv[i]          = __float2bfloat16(qkv_w[i]);          return; }
    if (i < W0+W1)        { g_wproj[i-W0]      = __float2bfloat16(proj_w[i-W0]);      return; }
    if (i < W0+W1+W2)     { g_wfc1[i-W0-W1]    = __float2bfloat16(fc1_w[i-W0-W1]);    return; }
    if (i < WTOT)         { g_wfc2[i-W0-W1-W2] = __float2bfloat16(fc2_w[i-W0-W1-W2]); return; }
    int j = i - WTOT;
    int h = j / (NTOK*NTOK);
    int e = j - h * (NTOK*NTOK);
    g_bias[h*NTOK*NTOK + e] = tbl[relidx[e]*HEADS + h];
}

// ---------------- fused transpose + LN1 + window scatter ----------------
__global__ __launch_bounds__(256) void k_ln1t(const float* __restrict__ x,
                                              const float* __restrict__ g,
                                              const float* __restrict__ be) {
    __shared__ float t[CDIM*33];
    int b  = blockIdx.y;
    int l0 = blockIdx.x * 32;
    int tid = threadIdx.x;
    int lane = tid & 31, warp = tid >> 5;

    const float* xb = x + (size_t)b * CDIM * LTOK + l0;
    {
        int l = tid & 31, cg = tid >> 5;
#pragma unroll
        for (int it = 0; it < 16; it++) {
            int c = it * 8 + cg;
            t[c * 33 + l] = xb[(size_t)c * LTOK + l];
        }
    }
    __syncthreads();

    float4 gg = reinterpret_cast<const float4*>(g)[lane];
    float4 bb = reinterpret_cast<const float4*>(be)[lane];
#pragma unroll
    for (int kk = 0; kk < 4; kk++) {
        int tt = warp * 4 + kk;
        int l  = l0 + tt;
        float4 v;
        v.x = t[(lane*4+0)*33 + tt];
        v.y = t[(lane*4+1)*33 + tt];
        v.z = t[(lane*4+2)*33 + tt];
        v.w = t[(lane*4+3)*33 + tt];
        int token = b * LTOK + l;
        reinterpret_cast<float4*>(g_xt + (size_t)token * CDIM)[lane] = v;
        float s  = v.x + v.y + v.z + v.w;
        float s2 = v.x*v.x + v.y*v.y + v.z*v.z + v.w*v.w;
        s  = warp_sum(s); s2 = warp_sum(s2);
        float mean = s * (1.f / CDIM);
        float var  = s2 * (1.f / CDIM) - mean * mean;
        float inv  = rsqrtf(var + 1e-5f);
        int hh = l / WWID, ww = l - hh * WWID;
        int h2 = hh - SHIFT; if (h2 < 0) h2 += HH;
        int w2 = ww - SHIFT; if (w2 < 0) w2 += WWID;
        int win  = (b << 8) + (h2 / WS) * 16 + (w2 / WS);
        int n    = (h2 % WS) * WS + (w2 % WS);
        int wrow = win * NTOK + n;
        store_bf16x4(g_xw + (size_t)wrow * CDIM + lane * 4,
                     (v.x - mean) * inv * gg.x + bb.x,
                     (v.y - mean) * inv * gg.y + bb.y,
                     (v.z - mean) * inv * gg.z + bb.z,
                     (v.w - mean) * inv * gg.w + bb.w);
    }
}

// ---------------- WMMA attention (R2-measured variant): one block per (window, head) ----
__global__ __launch_bounds__(128) void k_attn() {
    __shared__ __nv_bfloat16 sQ[64*40];
    __shared__ __nv_bfloat16 sK[64*40];
    __shared__ __nv_bfloat16 sV[64*40];
    __shared__ float         sS[64*68];
    __shared__ __nv_bfloat16 sP[64*72];
    __shared__ float         srinv[64];

    int bid  = blockIdx.x;
    int win  = bid >> 2;
    int head = bid & 3;
    int tid  = threadIdx.x;
    int warp = tid >> 5, lane = tid & 31;

    const __nv_bfloat16 zz = __float2bfloat16(0.f);
#pragma unroll
    for (int it = 0; it < 16; it++) {
        int e = it * 128 + tid;
        int n = e >> 5, d = e & 31;
        __nv_bfloat16 q = zz, k = zz, v = zz;
        if (n < NTOK) {
            size_t base = ((size_t)win * NTOK + n) * (3*CDIM) + head * HD + d;
            q = g_qkv[base];
            k = g_qkv[base + CDIM];
            v = g_qkv[base + 2*CDIM];
        }
        sQ[n*40 + d] = q;
        sK[n*40 + d] = k;
        sV[n*40 + d] = v;
    }
    for (int e = tid; e < 64*72/2; e += 128) reinterpret_cast<uint32_t*>(sP)[e] = 0u;
    __syncthreads();

    // S = Q K^T
    {
        int wrow = warp * 16;
        wmma::fragment<wmma::accumulator,16,16,16,float> s[4];
#pragma unroll
        for (int j = 0; j < 4; j++) wmma::fill_fragment(s[j], 0.f);
#pragma unroll
        for (int i = 0; i < 2; i++) {
            wmma::fragment<wmma::matrix_a,16,16,16,__nv_bfloat16,wmma::row_major> qa;
            wmma::load_matrix_sync(qa, &sQ[wrow*40 + 16*i], 40);
#pragma unroll
            for (int j = 0; j < 4; j++) {
                wmma::fragment<wmma::matrix_b,16,16,16,__nv_bfloat16,wmma::col_major> kb;
                wmma::load_matrix_sync(kb, &sK[(16*j)*40 + 16*i], 40);
                wmma::mma_sync(s[j], qa, kb, s[j]);
            }
        }
#pragma unroll
        for (int j = 0; j < 4; j++)
            wmma::store_matrix_sync(&sS[wrow*68 + 16*j], s[j], 68, wmma::mem_row_major);
    }
    __syncthreads();

    // warp-parallel softmax (unnormalized P, deferred 1/sum)
    {
        const float scale = 0.17677669529663687f;
        for (int r = warp; r < NTOK; r += 4) {
            const float* brow = &g_bias[head*NTOK*NTOK + r*NTOK];
            int c2 = lane + 32;
            float v1 = sS[r*68 + lane] * scale + brow[lane];
            float v2 = (c2 < NTOK) ? sS[r*68 + c2] * scale + brow[c2] : -1e30f;
            float mx = warp_max(fmaxf(v1, v2));
            float e1 = __expf(v1 - mx);
            float e2 = (c2 < NTOK) ? __expf(v2 - mx) : 0.f;
            float sum = warp_sum(e1 + e2);
            sP[r*72 + lane] = __float2bfloat16(e1);
            if (c2 < NTOK) sP[r*72 + c2] = __float2bfloat16(e2);
            if (lane == 0) srinv[r] = 1.f / sum;
        }
    }
    __syncthreads();

    // O = P V
    {
        int wrow = warp * 16;
        wmma::fragment<wmma::accumulator,16,16,16,float> o[2];
#pragma unroll
        for (int j = 0; j < 2; j++) wmma::fill_fragment(o[j], 0.f);
#pragma unroll
        for (int i = 0; i < 4; i++) {
            wmma::fragment<wmma::matrix_a,16,16,16,__nv_bfloat16,wmma::row_major> pa;
            wmma::load_matrix_sync(pa, &sP[wrow*72 + 16*i], 72);
#pragma unroll
            for (int j = 0; j < 2; j++) {
                wmma::fragment<wmma::matrix_b,16,16,16,__nv_bfloat16,wmma::row_major> vb;
                wmma::load_matrix_sync(vb, &sV[(16*i)*40 + 16*j], 40);
                wmma::mma_sync(o[j], pa, vb, o[j]);
            }
        }
        __syncthreads();
#pragma unroll
        for (int j = 0; j < 2; j++)
            wmma::store_matrix_sync(&sS[wrow*68 + 16*j], o[j], 68, wmma::mem_row_major);
    }
    __syncthreads();

#pragma unroll
    for (int it = 0; it < 13; it++) {
        int e = it * 128 + tid;
        if (e < NTOK * HD) {
            int n = e >> 5, d = e & 31;
            g_attnout[((size_t)win * NTOK + n) * CDIM + head * HD + d] =
                __float2bfloat16(sS[n*68 + d] * srinv[n]);
        }
    }
}

// ---------------- cp.async double-buffered WMMA GEMM, 128x128 tiles ----------------
// EPI: 0 = QKV (bias -> bf16, warp-patch direct), 1 = PROJ (staged, bias+residual+LN2),
//      2 = FC1 (bias + gelu -> bf16, warp-patch direct), 3 = FC2 (staged, residual+transpose)
#define TILEB 34816   // 128 x 136 bf16

extern __shared__ __align__(16) unsigned char gdyn[];

template<int NT128, int KT128, int EPI>
__device__ __forceinline__ void gemm_body(
    const __nv_bfloat16* __restrict__ A,
    const __nv_bfloat16* __restrict__ Bw,      // [K][N]
    const float* __restrict__ bias,
    float* __restrict__ outf,
    const float* __restrict__ ln_g,
    const float* __restrict__ ln_b)
{
    const int N = NT128 * 128, K = KT128 * 128;
    const int ABUF = (KT128 > 1) ? 2 : 1;
    unsigned char* sAb = gdyn;
    unsigned char* sBb = gdyn + ABUF * TILEB;
    const uint32_t sA32 = smem_u32(sAb), sB32 = smem_u32(sBb);

    const int tid = threadIdx.x;
    const int warp = tid >> 5, lane = tid & 31;
    const int bm = blockIdx.x * 128;
    const int wm = (warp & 3) * 32, wn = (warp >> 2) * 64;
    const int G = NT128 * KT128;

    auto issue = [&](int g) {
        int nc = g / KT128, kc = g % KT128;
        {
            const __nv_bfloat16* src = Bw + (size_t)(kc*128) * N + nc*128;
            uint32_t sb = sB32 + (uint32_t)(g & 1) * TILEB;
#pragma unroll
            for (int it = 0; it < 8; it++) {
                int idx = it * 256 + tid;
                int r = idx >> 4, c = idx & 15;
                cpa16(sb + r*272 + c*16, src + (size_t)r * N + c*8);
            }
        }
        if (KT128 > 1 || g == 0) {
            const __nv_bfloat16* src = A + (size_t)bm * K + kc*128;
            uint32_t sa = sA32 + (KT128 > 1 ? (uint32_t)(g & 1) * TILEB : 0u);
#pragma unroll
            for (int it = 0; it < 8; it++) {
                int idx = it * 256 + tid;
                int r = idx >> 4, c = idx & 15;
                cpa16(sa + r*272 + c*16, src + (size_t)r * K + c*8);
            }
        }
        cpa_commit();
    };

    issue(0);
    if (G > 1) issue(1);

    wmma::fragment<wmma::accumulator,16,16,16,float> acc[2][4];

#pragma unroll 1
    for (int g = 0; g < G; g++) {
        int kc = g % KT128;
        if (g + 1 < G) asm volatile("cp.async.wait_group 1;" ::: "memory");
        else           asm volatile("cp.async.wait_group 0;" ::: "memory");
        __syncthreads();

        if (kc == 0) {
#pragma unroll
            for (int i = 0; i < 2; i++)
#pragma unroll
                for (int j = 0; j < 4; j++) wmma::fill_fragment(acc[i][j], 0.f);
        }
        const __nv_bfloat16* pA = reinterpret_cast<const __nv_bfloat16*>(
            sAb + (KT128 > 1 ? (size_t)(g & 1) * TILEB : 0));
        const __nv_bfloat16* pB = reinterpret_cast<const __nv_bfloat16*>(
            sBb + (size_t)(g & 1) * TILEB);
#pragma unroll
        for (int kk = 0; kk < 8; kk++) {
            wmma::fragment<wmma::matrix_a,16,16,16,__nv_bfloat16,wmma::row_major> af[2];
#pragma unroll
            for (int i = 0; i < 2; i++)
                wmma::load_matrix_sync(af[i], &pA[(wm + 16*i)*136 + kk*16], 136);
#pragma unroll
            for (int j = 0; j < 4; j++) {
                wmma::fragment<wmma::matrix_b,16,16,16,__nv_bfloat16,wmma::row_major> bf;
                wmma::load_matrix_sync(bf, &pB[(kk*16)*136 + wn + 16*j], 136);
#pragma unroll
                for (int i = 0; i < 2; i++)
                    wmma::mma_sync(acc[i][j], af[i], bf, acc[i][j]);
            }
        }
        __syncthreads();

        if (kc == KT128 - 1) {
            int nc = g / KT128;
            float* sC = reinterpret_cast<float*>(sBb + (size_t)(g & 1) * TILEB);

            if (EPI == 0 || EPI == 2) {
                // warp-private patch epilogue: no block syncs inside
                const int ncol = (EPI == 0) ? 3*CDIM : MLP;
                __nv_bfloat16* base = (EPI == 0) ? g_qkv : g_hh;
                float* patch = sC + warp * 320;            // 16x16 tile, ld=20 (1280B/warp)
                int r2 = lane >> 1;
                int cc = (lane & 1) * 8;
#pragma unroll
                for (int i = 0; i < 2; i++) {
#pragma unroll
                    for (int j = 0; j < 4; j++) {
                        wmma::store_matrix_sync(patch, acc[i][j], 20, wmma::mem_row_major);
                        __syncwarp();
                        float4 v0 = *reinterpret_cast<float4*>(patch + r2*20 + cc);
                        float4 v1 = *reinterpret_cast<float4*>(patch + r2*20 + cc + 4);
                        __syncwarp();
                        int gr = bm + wm + 16*i + r2;
                        int gc = nc*128 + wn + 16*j + cc;
                        float4 b0 = __ldg(reinterpret_cast<const float4*>(bias + gc));
                        float4 b1 = __ldg(reinterpret_cast<const float4*>(bias + gc + 4));
                        v0.x += b0.x; v0.y += b0.y; v0.z += b0.z; v0.w += b0.w;
                        v1.x += b1.x; v1.y += b1.y; v1.z += b1.z; v1.w += b1.w;
                        if (EPI == 2) {
                            const float is2 = 0.70710678118654752f;
                            v0.x = 0.5f*v0.x*(1.f+erff(v0.x*is2));
                            v0.y = 0.5f*v0.y*(1.f+erff(v0.y*is2));
                            v0.z = 0.5f*v0.z*(1.f+erff(v0.z*is2));
                            v0.w = 0.5f*v0.w*(1.f+erff(v0.w*is2));
                            v1.x = 0.5f*v1.x*(1.f+erff(v1.x*is2));
                            v1.y = 0.5f*v1.y*(1.f+erff(v1.y*is2));
                            v1.z = 0.5f*v1.z*(1.f+erff(v1.z*is2));
                            v1.w = 0.5f*v1.w*(1.f+erff(v1.w*is2));
                        }
                        uint4 o;
                        o.x = pack2(v0.x, v0.y); o.y = pack2(v0.z, v0.w);
                        o.z = pack2(v1.x, v1.y); o.w = pack2(v1.z, v1.w);
                        *reinterpret_cast<uint4*>(base + (size_t)gr * ncol + gc) = o;
                    }
                }
                __syncthreads();   // patches (in B buffer) dead before next cp.async
            } else {
#pragma unroll
                for (int h2 = 0; h2 < 2; h2++) {
                    if (((warp & 3) >> 1) == h2) {
                        int wl = wm - 64 * h2;
#pragma unroll
                        for (int i = 0; i < 2; i++)
#pragma unroll
                            for (int j = 0; j < 4; j++)
                                wmma::store_matrix_sync(&sC[(wl + 16*i)*132 + wn + 16*j],
                                                        acc[i][j], 132, wmma::mem_row_major);
                    }
                    __syncthreads();

                    if (EPI == 1) {
                        float4 pb = reinterpret_cast<const float4*>(bias)[lane];
                        float4 gg = reinterpret_cast<const float4*>(ln_g)[lane];
                        float4 lb = reinterpret_cast<const float4*>(ln_b)[lane];
                        for (int r = warp; r < 64; r += 8) {
                            int token = winrow_to_token(bm + 64*h2 + r);
                            float4 v = *reinterpret_cast<float4*>(&sC[r*132 + lane*4]);
                            float4 x = reinterpret_cast<const float4*>(g_xt + (size_t)token*CDIM)[lane];
                            float4 y;
                            y.x = v.x + pb.x + x.x;  y.y = v.y + pb.y + x.y;
                            y.z = v.z + pb.z + x.z;  y.w = v.w + pb.w + x.w;
                            reinterpret_cast<float4*>(g_y + (size_t)token*CDIM)[lane] = y;
                            float s  = y.x + y.y + y.z + y.w;
                            float s2 = y.x*y.x + y.y*y.y + y.z*y.z + y.w*y.w;
                            s = warp_sum(s); s2 = warp_sum(s2);
                            float mean = s * (1.f / CDIM);
                            float var  = s2 * (1.f / CDIM) - mean * mean;
                            float inv  = rsqrtf(var + 1e-5f);
                            store_bf16x4(g_h + (size_t)token*CDIM + lane*4,
                                         (y.x - mean) * inv * gg.x + lb.x,
                                         (y.y - mean) * inv * gg.y + lb.y,
                                         (y.z - mean) * inv * gg.z + lb.z,
                                         (y.w - mean) * inv * gg.w + lb.w);
                        }
                    } else {
                        int row0 = bm + 64*h2;
                        for (int e = tid; e < 64*128; e += 256) {
                            int r = e >> 7, c = e & 127;
                            sC[r*132 + c] += bias[c] + g_y[(size_t)(row0 + r)*CDIM + c];
                        }
                        __syncthreads();
                        int b  = row0 / LTOK;
                        int l0 = row0 - b * LTOK;
                        float* ob = outf + (size_t)b * CDIM * LTOK + l0;
                        int l = tid & 63, cb = tid >> 6;
#pragma unroll
                        for (int it = 0; it < 32; it++) {
                            int c = it * 4 + cb;
                            ob[(size_t)c * LTOK + l] = sC[l*132 + c];
                        }
                    }
                    __syncthreads();
                }
            }
        }
        if (g + 2 < G) issue(g + 2);
    }
}

__global__ __launch_bounds__(256) void k_gemm_qkv(const float* bias) {
    gemm_body<3,1,0>(g_xw, g_wqkv, bias, nullptr, nullptr, nullptr);
}
__global__ __launch_bounds__(256) void k_gemm_proj(const float* bias, const float* g, const float* b2) {
    gemm_body<1,1,1>(g_attnout, g_wproj, bias, nullptr, g, b2);
}
__global__ __launch_bounds__(256) void k_gemm_fc1(const float* bias) {
    gemm_body<4,1,2>(g_h, g_wfc1, bias, nullptr, nullptr, nullptr);
}
__global__ __launch_bounds__(256) void k_gemm_fc2(const float* bias, float* out) {
    gemm_body<1,4,3>(g_hh, g_wfc2, bias, out, nullptr, nullptr);
}

// ---------------- launch ----------------
extern "C" void kernel_launch(void* const* d_in, const int* in_sizes, int n_in,
                              void* d_out, int out_size) {
    const float* x      = (const float*)d_in[0];
    const float* n1g    = (const float*)d_in[1];
    const float* n1b    = (const float*)d_in[2];
    const float* qkv_w  = (const float*)d_in[3];
    const float* qkv_b  = (const float*)d_in[4];
    const float* tbl    = (const float*)d_in[5];
    const int*   relidx = (const int*)d_in[6];
    const float* proj_w = (const float*)d_in[7];
    const float* proj_b = (const float*)d_in[8];
    const float* n2g    = (const float*)d_in[9];
    const float* n2b    = (const float*)d_in[10];
    const float* fc1_w  = (const float*)d_in[11];
    const float* fc1_b  = (const float*)d_in[12];
    const float* fc2_w  = (const float*)d_in[13];
    const float* fc2_b  = (const float*)d_in[14];
    float* out = (float*)d_out;

    const int GSM_G1  = 3 * TILEB;        // 104448: qkv/proj/fc1 (A + 2B)
    const int GSM_FC2 = 4 * TILEB;        // 139264: fc2 (2A + 2B)

    cudaFuncSetAttribute(k_gemm_qkv,  cudaFuncAttributeMaxDynamicSharedMemorySize, GSM_G1);
    cudaFuncSetAttribute(k_gemm_proj, cudaFuncAttributeMaxDynamicSharedMemorySize, GSM_G1);
    cudaFuncSetAttribute(k_gemm_fc1,  cudaFuncAttributeMaxDynamicSharedMemorySize, GSM_G1);
    cudaFuncSetAttribute(k_gemm_fc2,  cudaFuncAttributeMaxDynamicSharedMemorySize, GSM_FC2);

    k_setup<<<(SETUP_TOT + 255)/256, 256>>>(qkv_w, proj_w, fc1_w, fc2_w, tbl, relidx);
    k_ln1t<<<dim3(LTOK/32, BB), 256>>>(x, n1g, n1b);
    k_gemm_qkv<<<MTOK/128, 256, GSM_G1>>>(qkv_b);
    k_attn<<<NWIN*HEADS, 128>>>();
    k_gemm_proj<<<MTOK/128, 256, GSM_G1>>>(proj_b, n2g, n2b);
    k_gemm_fc1<<<MTOK/128, 256, GSM_G1>>>(fc1_b);
    k_gemm_fc2<<<MTOK/128, 256, GSM_FC2>>>(fc2_b, out);
}